// round 5
// baseline (speedup 1.0000x reference)
#include <cuda_runtime.h>

// QSoftmax: out = clip(rint((LUT[inp] - exp_zero) * (1/rowsum(LUT[inp]) - 1/exp_zero)
//                           * (exp_scale * (1/exp_scale) / normed_scale) + normed_zero), 0, 255)
// inp: int32 [8, 2048, 2048], LUT: float32 [256], 4 scalar float params, out: float32.
//
// Single-pass, one CTA per row (S=2048). 256 threads x 8 elements/thread.
// Gathered LUT values stay in registers across the row reduction -> input read once.

#define S_LEN 2048
#define THREADS 256
#define PER_THREAD 8   // 2048 / 256

__global__ __launch_bounds__(THREADS, 8)
void qsoftmax_kernel(const int* __restrict__ inp,
                     const float* __restrict__ lut,
                     const float* __restrict__ exp_scale_p,
                     const float* __restrict__ exp_zero_p,
                     const float* __restrict__ normed_scale_p,
                     const float* __restrict__ normed_zero_p,
                     float* __restrict__ out)
{
    __shared__ float slut[256];
    __shared__ float swsum[THREADS / 32];

    const int tid = threadIdx.x;
    slut[tid] = lut[tid];
    __syncthreads();

    const long long base = (long long)blockIdx.x * S_LEN + (long long)tid * PER_THREAD;

    // 128-bit vector loads: 8 int32 per thread
    const int4* in4 = reinterpret_cast<const int4*>(inp + base);
    int4 a = in4[0];
    int4 b = in4[1];

    float e[PER_THREAD];
    e[0] = slut[a.x]; e[1] = slut[a.y]; e[2] = slut[a.z]; e[3] = slut[a.w];
    e[4] = slut[b.x]; e[5] = slut[b.y]; e[6] = slut[b.z]; e[7] = slut[b.w];

    // Local tree sum
    float s = ((e[0] + e[1]) + (e[2] + e[3])) + ((e[4] + e[5]) + (e[6] + e[7]));

    // Warp reduction
    #pragma unroll
    for (int off = 16; off > 0; off >>= 1)
        s += __shfl_xor_sync(0xffffffffu, s, off);

    const int wid = tid >> 5;
    if ((tid & 31) == 0) swsum[wid] = s;
    __syncthreads();

    // Broadcast cross-warp sum (8 LDS broadcasts per thread — cheap)
    float rowsum = ((swsum[0] + swsum[1]) + (swsum[2] + swsum[3]))
                 + ((swsum[4] + swsum[5]) + (swsum[6] + swsum[7]));

    const float exp_scale    = exp_scale_p[0];
    const float exp_zero     = exp_zero_p[0];
    const float normed_scale = normed_scale_p[0];
    const float normed_zero  = normed_zero_p[0];

    const float denom      = 1.0f / rowsum;
    const float multiplier = exp_scale * (1.0f / exp_scale) / normed_scale;
    const float b_zeroed   = denom - 1.0f / exp_zero;
    const float factor     = b_zeroed * multiplier;

    float4 o0, o1;
    o0.x = fminf(fmaxf(rintf((e[0] - exp_zero) * factor + normed_zero), 0.0f), 255.0f);
    o0.y = fminf(fmaxf(rintf((e[1] - exp_zero) * factor + normed_zero), 0.0f), 255.0f);
    o0.z = fminf(fmaxf(rintf((e[2] - exp_zero) * factor + normed_zero), 0.0f), 255.0f);
    o0.w = fminf(fmaxf(rintf((e[3] - exp_zero) * factor + normed_zero), 0.0f), 255.0f);
    o1.x = fminf(fmaxf(rintf((e[4] - exp_zero) * factor + normed_zero), 0.0f), 255.0f);
    o1.y = fminf(fmaxf(rintf((e[5] - exp_zero) * factor + normed_zero), 0.0f), 255.0f);
    o1.z = fminf(fmaxf(rintf((e[6] - exp_zero) * factor + normed_zero), 0.0f), 255.0f);
    o1.w = fminf(fmaxf(rintf((e[7] - exp_zero) * factor + normed_zero), 0.0f), 255.0f);

    float4* out4 = reinterpret_cast<float4*>(out + base);
    out4[0] = o0;
    out4[1] = o1;
}

extern "C" void kernel_launch(void* const* d_in, const int* in_sizes, int n_in,
                              void* d_out, int out_size)
{
    const int*   inp          = (const int*)d_in[0];
    const float* lut          = (const float*)d_in[1];
    const float* exp_scale    = (const float*)d_in[2];
    const float* exp_zero     = (const float*)d_in[3];
    const float* normed_scale = (const float*)d_in[4];
    const float* normed_zero  = (const float*)d_in[5];
    float*       out          = (float*)d_out;

    const int num_rows = out_size / S_LEN;  // 8 * 2048 = 16384
    qsoftmax_kernel<<<num_rows, THREADS>>>(inp, lut, exp_scale, exp_zero,
                                           normed_scale, normed_zero, out);
}